// round 1
// baseline (speedup 1.0000x reference)
#include <cuda_runtime.h>
#include <cuda_bf16.h>
#include <math_constants.h>
#include <float.h>

#define NPTS 100000
#define NRAYS 4096
#define KTOP 10
#define SEG 64
#define SEGN 1563           // ceil(100000/64)
#define RAYS_PER_BLK 256
#define NCAND (SEG * KTOP)  // 640 candidates per ray

// ---- scratch (no allocations allowed) ----
__device__ float4 g_pts[NPTS + 32];                 // {x, y, z, ||p||^2}
__device__ float  g_cand_sq [NRAYS * NCAND];
__device__ int    g_cand_idx[NRAYS * NCAND];

// ============================================================
// Kernel A: precompute packed point + squared norm
// ============================================================
__global__ void k_prep(const float* __restrict__ xyz) {
    int i = blockIdx.x * 256 + threadIdx.x;
    if (i < NPTS) {
        float x = xyz[3 * i + 0];
        float y = xyz[3 * i + 1];
        float z = xyz[3 * i + 2];
        float pn = fmaf(x, x, fmaf(y, y, z * z));
        g_pts[i] = make_float4(x, y, z, pn);
    }
}

// ============================================================
// Kernel B: brute-force scan, per-(ray, segment) register top-10
// grid = (NRAYS/256, SEG), block = 256 (thread owns one ray)
// ============================================================
__global__ __launch_bounds__(RAYS_PER_BLK) void k_scan(const float* __restrict__ rays_o,
                                                       const float* __restrict__ rays_d) {
    __shared__ float4 sp[SEGN];

    const int seg  = blockIdx.y;
    const int base = seg * SEGN;
    const int cnt  = min(SEGN, NPTS - base);

    // cooperative coalesced stage of this segment's points
    for (int i = threadIdx.x; i < cnt; i += RAYS_PER_BLK)
        sp[i] = g_pts[base + i];
    __syncthreads();

    const int r = blockIdx.x * RAYS_PER_BLK + threadIdx.x;
    const float cx = fmaf(rays_d[3 * r + 0], 3.0f, rays_o[3 * r + 0]);
    const float cy = fmaf(rays_d[3 * r + 1], 3.0f, rays_o[3 * r + 1]);
    const float cz = fmaf(rays_d[3 * r + 2], 3.0f, rays_o[3 * r + 2]);
    const float cn  = fmaf(cx, cx, fmaf(cy, cy, cz * cz));
    const float c2x = -2.0f * cx, c2y = -2.0f * cy, c2z = -2.0f * cz;

    // sorted ascending top-K in s-space (s = ||p||^2 - 2 c.p ; sq = s + cn)
    float sq[KTOP];
    int   ix[KTOP];
#pragma unroll
    for (int j = 0; j < KTOP; ++j) { sq[j] = FLT_MAX; ix[j] = 0x7fffffff; }

#pragma unroll 4
    for (int i = 0; i < cnt; ++i) {
        float4 p = sp[i];   // warp-uniform address -> conflict-free broadcast
        float s = fmaf(p.x, c2x, fmaf(p.y, c2y, fmaf(p.z, c2z, p.w)));
        if (s < sq[KTOP - 1]) {           // ~0.1% hit rate
            float v = s; int vi = base + i;
#pragma unroll
            for (int j = 0; j < KTOP; ++j) {
                if (v < sq[j]) {
                    float tf = sq[j]; sq[j] = v;  v  = tf;
                    int   ti = ix[j]; ix[j] = vi; vi = ti;
                }
            }
        }
    }

    const int ob = (r * SEG + seg) * KTOP;
#pragma unroll
    for (int j = 0; j < KTOP; ++j) {
        g_cand_sq [ob + j] = sq[j] + cn;   // back to true squared distance
        g_cand_idx[ob + j] = ix[j];
    }
}

// ============================================================
// Kernel C: merge 640 candidates/ray -> top-10, then shade.
// One warp per ray; block = 256 (8 rays), grid = NRAYS/8.
// ============================================================
__device__ __forceinline__ float sigmoidf_(float x) {
    return 1.0f / (1.0f + expf(-x));
}

__global__ __launch_bounds__(256) void k_merge(const float* __restrict__ opacity,
                                               const float* __restrict__ fdc,
                                               float* __restrict__ out) {
    const int warp = threadIdx.x >> 5;
    const int lane = threadIdx.x & 31;
    const int r    = blockIdx.x * 8 + warp;
    const int cb   = r * NCAND;

    // per-lane sorted top-10 over 20 coalesced candidates
    float lsq[KTOP]; int lix[KTOP];
#pragma unroll
    for (int j = 0; j < KTOP; ++j) { lsq[j] = CUDART_INF_F; lix[j] = 0x7fffffff; }

    for (int t = lane; t < NCAND; t += 32) {
        float v  = g_cand_sq [cb + t];
        int   vi = g_cand_idx[cb + t];
        bool better = (v < lsq[KTOP - 1]) ||
                      (v == lsq[KTOP - 1] && vi < lix[KTOP - 1]);
        if (better) {
#pragma unroll
            for (int j = 0; j < KTOP; ++j) {
                bool lt = (v < lsq[j]) || (v == lsq[j] && vi < lix[j]);
                if (lt) {
                    float tf = lsq[j]; lsq[j] = v;  v  = tf;
                    int   ti = lix[j]; lix[j] = vi; vi = ti;
                }
            }
        }
    }

    // 10-round warp merge: each round extracts the global (sq,idx) min
    int p = 0;
    float my_sq = 0.0f; int my_idx = 0;
    for (int k = 0; k < KTOP; ++k) {
        float v  = (p < KTOP) ? lsq[p] : CUDART_INF_F;
        int   vi = (p < KTOP) ? lix[p] : 0x7fffffff;
        int   src = lane;
#pragma unroll
        for (int off = 16; off; off >>= 1) {
            float ov = __shfl_xor_sync(0xffffffffu, v,   off);
            int   oi = __shfl_xor_sync(0xffffffffu, vi,  off);
            int   os = __shfl_xor_sync(0xffffffffu, src, off);
            if (ov < v || (ov == v && oi < vi)) { v = ov; vi = oi; src = os; }
        }
        if (lane == src) ++p;            // winner pops its local head
        if (lane == k)  { my_sq = v; my_idx = vi; }
    }

    // shading: lanes 0..9 own one selected point each
    float w = 0.0f, cr = 0.0f, cg = 0.0f, cb3 = 0.0f;
    if (lane < KTOP) {
        float d  = sqrtf(fmaxf(my_sq, 0.0f));
        float os = sigmoidf_(opacity[my_idx]);
        w = expf(-0.1f * d) * os;
        cr  = w * sigmoidf_(fdc[3 * my_idx + 0]);
        cg  = w * sigmoidf_(fdc[3 * my_idx + 1]);
        cb3 = w * sigmoidf_(fdc[3 * my_idx + 2]);
    }
    float ws = w;
#pragma unroll
    for (int off = 16; off; off >>= 1) {
        ws  += __shfl_xor_sync(0xffffffffu, ws,  off);
        cr  += __shfl_xor_sync(0xffffffffu, cr,  off);
        cg  += __shfl_xor_sync(0xffffffffu, cg,  off);
        cb3 += __shfl_xor_sync(0xffffffffu, cb3, off);
    }
    ws += 1e-8f;
    if (lane == 0) {
        out[3 * r + 0] = cr  / ws;
        out[3 * r + 1] = cg  / ws;
        out[3 * r + 2] = cb3 / ws;
    }
}

// ============================================================
extern "C" void kernel_launch(void* const* d_in, const int* in_sizes, int n_in,
                              void* d_out, int out_size) {
    const float* rays_o  = (const float*)d_in[0];
    const float* rays_d  = (const float*)d_in[1];
    const float* xyz     = (const float*)d_in[2];
    const float* fdc     = (const float*)d_in[3];
    const float* opacity = (const float*)d_in[4];
    float* out = (float*)d_out;

    k_prep<<<(NPTS + 255) / 256, 256>>>(xyz);
    dim3 gridB(NRAYS / RAYS_PER_BLK, SEG);
    k_scan<<<gridB, RAYS_PER_BLK>>>(rays_o, rays_d);
    k_merge<<<NRAYS / 8, 256>>>(opacity, fdc, out);
}

// round 2
// speedup vs baseline: 1.1686x; 1.1686x over previous
#include <cuda_runtime.h>
#include <cuda_bf16.h>
#include <math_constants.h>
#include <float.h>

#define NPTS   100000
#define NRAYS  4096
#define KTOP   10
#define SUBLEN 128
#define NSUB   782          // ceil(100000/128); last subchunk has 32 points
#define MAXSUB 64           // per-ray flagged-subchunk cap (rank(T) <~30 w.h.p.)
#define CANDMAX 128         // per-ray candidate cap

// ---------------- scratch (no allocations allowed) ----------------
__device__ float4      g_pts [NPTS];            // {x,y,z,||p||^2}
__device__ ulonglong2  g_ptsd[NPTS * 2];        // duplicated pairs {xx,yy},{zz,ww}
__device__ float4      g_ctr [NRAYS];           // {cx,cy,cz,||c||^2}
__device__ float       g_submin[NSUB * NRAYS];  // [sub][ray] min of s
__device__ float       g_T   [NRAYS];
__device__ int         g_nsub[NRAYS];
__device__ int         g_sublist[NRAYS * MAXSUB];
__device__ int         g_cnt [NRAYS];
__device__ float       g_cs  [NRAYS * CANDMAX];
__device__ int         g_ci  [NRAYS * CANDMAX];

// ---------------- f32x2 packed helpers ----------------
__device__ __forceinline__ unsigned long long pack2(float lo, float hi) {
    unsigned long long r;
    asm("mov.b64 %0, {%1, %2};" : "=l"(r) : "f"(lo), "f"(hi));
    return r;
}
__device__ __forceinline__ unsigned long long fma2(unsigned long long a,
                                                   unsigned long long b,
                                                   unsigned long long c) {
    unsigned long long d;
    asm("fma.rn.f32x2 %0, %1, %2, %3;" : "=l"(d) : "l"(a), "l"(b), "l"(c));
    return d;
}
__device__ __forceinline__ void unpack2(unsigned long long v, float& lo, float& hi) {
    asm("mov.b64 {%0, %1}, %2;" : "=f"(lo), "=f"(hi) : "l"(v));
}

// ============================================================
// Kernel 1: prep — pack points (plain + duplicated), ray centers, zero counters
// ============================================================
__global__ void k_prep(const float* __restrict__ xyz,
                       const float* __restrict__ rays_o,
                       const float* __restrict__ rays_d) {
    int i = blockIdx.x * 256 + threadIdx.x;
    if (i < NPTS) {
        float x = xyz[3 * i + 0];
        float y = xyz[3 * i + 1];
        float z = xyz[3 * i + 2];
        float pn = fmaf(x, x, fmaf(y, y, z * z));
        g_pts[i] = make_float4(x, y, z, pn);
        ulonglong2 a, b;
        a.x = pack2(x, x);  a.y = pack2(y, y);
        b.x = pack2(z, z);  b.y = pack2(pn, pn);
        g_ptsd[2 * i]     = a;
        g_ptsd[2 * i + 1] = b;
    }
    if (i < NRAYS) {
        float cx = fmaf(rays_d[3 * i + 0], 3.0f, rays_o[3 * i + 0]);
        float cy = fmaf(rays_d[3 * i + 1], 3.0f, rays_o[3 * i + 1]);
        float cz = fmaf(rays_d[3 * i + 2], 3.0f, rays_o[3 * i + 2]);
        float cn = fmaf(cx, cx, fmaf(cy, cy, cz * cz));
        g_ctr[i] = make_float4(cx, cy, cz, cn);
        g_cnt[i] = 0;
    }
}

// ============================================================
// Kernel 2: branchless min of s per (ray, 128-pt subchunk).
// Thread owns 4 rays (2 f32x2 pairs); block = 256 thr = 1024 rays.
// grid = (NRAYS/1024, NSUB).
// ============================================================
__global__ __launch_bounds__(256) void k_minsub() {
    __shared__ ulonglong2 sp[2 * SUBLEN];   // 4 KB duplicated points

    const int sub  = blockIdx.y;
    const int base = sub * SUBLEN;
    const int cnt  = min(SUBLEN, NPTS - base);

    for (int i = threadIdx.x; i < 2 * cnt; i += 256)
        sp[i] = g_ptsd[2 * base + i];
    __syncthreads();

    const int t  = threadIdx.x;
    const int r0 = blockIdx.x * 1024 + t;      // rays r0, r0+256, r0+512, r0+768
    float4 cA = g_ctr[r0];
    float4 cB = g_ctr[r0 + 256];
    float4 cC = g_ctr[r0 + 512];
    float4 cD = g_ctr[r0 + 768];
    const unsigned long long ax = pack2(-2.0f * cA.x, -2.0f * cB.x);
    const unsigned long long ay = pack2(-2.0f * cA.y, -2.0f * cB.y);
    const unsigned long long az = pack2(-2.0f * cA.z, -2.0f * cB.z);
    const unsigned long long bx = pack2(-2.0f * cC.x, -2.0f * cD.x);
    const unsigned long long by = pack2(-2.0f * cC.y, -2.0f * cD.y);
    const unsigned long long bz = pack2(-2.0f * cC.z, -2.0f * cD.z);

    float m0 = FLT_MAX, m1 = FLT_MAX, m2 = FLT_MAX, m3 = FLT_MAX;

#pragma unroll 8
    for (int i = 0; i < cnt; ++i) {
        ulonglong2 v0 = sp[2 * i];       // {xx, yy}
        ulonglong2 v1 = sp[2 * i + 1];   // {zz, ww}
        unsigned long long sAB = fma2(v0.x, ax, fma2(v0.y, ay, fma2(v1.x, az, v1.y)));
        unsigned long long sCD = fma2(v0.x, bx, fma2(v0.y, by, fma2(v1.x, bz, v1.y)));
        float lo, hi;
        unpack2(sAB, lo, hi); m0 = fminf(m0, lo); m1 = fminf(m1, hi);
        unpack2(sCD, lo, hi); m2 = fminf(m2, lo); m3 = fminf(m3, hi);
    }

    g_submin[sub * NRAYS + r0]       = m0;
    g_submin[sub * NRAYS + r0 + 256] = m1;
    g_submin[sub * NRAYS + r0 + 512] = m2;
    g_submin[sub * NRAYS + r0 + 768] = m3;
}

// ============================================================
// Kernel 3: per-ray threshold T = 10th smallest of 782 subchunk minima
// (valid upper bound on the true 10th-smallest distance), then flag
// subchunks with min <= T. Thread per ray; loads coalesced ([sub][ray]).
// ============================================================
__global__ void k_thresh() {
    int r = blockIdx.x * 256 + threadIdx.x;
    float top[KTOP];
#pragma unroll
    for (int j = 0; j < KTOP; ++j) top[j] = FLT_MAX;

    for (int s = 0; s < NSUB; ++s) {
        float v = g_submin[s * NRAYS + r];
        if (v < top[KTOP - 1]) {
#pragma unroll
            for (int j = 0; j < KTOP; ++j) {
                if (v < top[j]) { float tf = top[j]; top[j] = v; v = tf; }
            }
        }
    }
    float T = top[KTOP - 1];
    g_T[r] = T;

    int n = 0;
    for (int s = 0; s < NSUB; ++s) {
        if (g_submin[s * NRAYS + r] <= T && n < MAXSUB)
            g_sublist[r * MAXSUB + n++] = s;
    }
    g_nsub[r] = n;
}

// ============================================================
// Kernel 4: emit — warp per ray; rescan only flagged subchunks (~10-12),
// emit every point with s <= T (superset of true top-10; same fmaf chain
// as k_minsub halves -> bitwise-consistent).
// ============================================================
__global__ __launch_bounds__(256) void k_emit() {
    const int warp = threadIdx.x >> 5;
    const int lane = threadIdx.x & 31;
    const int r    = blockIdx.x * 8 + warp;

    float4 c = g_ctr[r];
    const float c2x = -2.0f * c.x, c2y = -2.0f * c.y, c2z = -2.0f * c.z;
    const float T = g_T[r];
    const int   n = g_nsub[r];

    for (int k = 0; k < n; ++k) {
        int sub  = g_sublist[r * MAXSUB + k];
        int base = sub * SUBLEN;
        int cnt  = min(SUBLEN, NPTS - base);
        for (int j = lane; j < cnt; j += 32) {
            float4 p = g_pts[base + j];
            float s = fmaf(p.x, c2x, fmaf(p.y, c2y, fmaf(p.z, c2z, p.w)));
            if (s <= T) {
                int pos = atomicAdd(&g_cnt[r], 1);
                if (pos < CANDMAX) {
                    g_cs[r * CANDMAX + pos] = s;
                    g_ci[r * CANDMAX + pos] = base + j;
                }
            }
        }
    }
}

// ============================================================
// Kernel 5: shade — warp per ray; exact lexicographic (s, idx) top-10
// of <=128 candidates, then sigmoid/exp weighting.
// ============================================================
__device__ __forceinline__ float sigmoidf_(float x) {
    return 1.0f / (1.0f + expf(-x));
}

__global__ __launch_bounds__(256) void k_shade(const float* __restrict__ opacity,
                                               const float* __restrict__ fdc,
                                               float* __restrict__ out) {
    const int warp = threadIdx.x >> 5;
    const int lane = threadIdx.x & 31;
    const int r    = blockIdx.x * 8 + warp;
    const float cn = g_ctr[r].w;
    const int m = min(g_cnt[r], CANDMAX);

    // up to 4 candidates per lane, sorted ascending lexicographically
    float ls[4]; int li[4];
#pragma unroll
    for (int j = 0; j < 4; ++j) {
        int t = lane + 32 * j;
        if (t < m) { ls[j] = g_cs[r * CANDMAX + t]; li[j] = g_ci[r * CANDMAX + t]; }
        else       { ls[j] = CUDART_INF_F;          li[j] = 0x7fffffff; }
    }
    // sort-4 network on (s, idx): (0,1)(2,3)(0,2)(1,3)(1,2)
#define CSWP(a, b) { \
        bool sw = (ls[b] < ls[a]) || (ls[b] == ls[a] && li[b] < li[a]); \
        if (sw) { float tf = ls[a]; ls[a] = ls[b]; ls[b] = tf; \
                  int   ti = li[a]; li[a] = li[b]; li[b] = ti; } }
    CSWP(0, 1) CSWP(2, 3) CSWP(0, 2) CSWP(1, 3) CSWP(1, 2)
#undef CSWP

    // 10 extraction rounds: warp-wide lexicographic argmin, winner pops head
    float my_s = 0.0f; int my_i = 0;
    for (int k = 0; k < KTOP; ++k) {
        float v  = ls[0];
        int   vi = li[0];
        int   src = lane;
#pragma unroll
        for (int off = 16; off; off >>= 1) {
            float ov = __shfl_xor_sync(0xffffffffu, v,   off);
            int   oi = __shfl_xor_sync(0xffffffffu, vi,  off);
            int   os = __shfl_xor_sync(0xffffffffu, src, off);
            if (ov < v || (ov == v && oi < vi)) { v = ov; vi = oi; src = os; }
        }
        if (lane == src) {   // shift down
            ls[0] = ls[1]; li[0] = li[1];
            ls[1] = ls[2]; li[1] = li[2];
            ls[2] = ls[3]; li[2] = li[3];
            ls[3] = CUDART_INF_F; li[3] = 0x7fffffff;
        }
        if (lane == k) { my_s = v; my_i = vi; }
    }

    // shading: lanes 0..9 own one selected point each
    float w = 0.0f, cr = 0.0f, cg = 0.0f, cb = 0.0f;
    if (lane < KTOP) {
        float sq = my_s + cn;
        float d  = sqrtf(fmaxf(sq, 0.0f));
        float os = sigmoidf_(opacity[my_i]);
        w  = expf(-0.1f * d) * os;
        cr = w * sigmoidf_(fdc[3 * my_i + 0]);
        cg = w * sigmoidf_(fdc[3 * my_i + 1]);
        cb = w * sigmoidf_(fdc[3 * my_i + 2]);
    }
    float ws = w;
#pragma unroll
    for (int off = 16; off; off >>= 1) {
        ws += __shfl_xor_sync(0xffffffffu, ws, off);
        cr += __shfl_xor_sync(0xffffffffu, cr, off);
        cg += __shfl_xor_sync(0xffffffffu, cg, off);
        cb += __shfl_xor_sync(0xffffffffu, cb, off);
    }
    ws += 1e-8f;
    if (lane == 0) {
        out[3 * r + 0] = cr / ws;
        out[3 * r + 1] = cg / ws;
        out[3 * r + 2] = cb / ws;
    }
}

// ============================================================
extern "C" void kernel_launch(void* const* d_in, const int* in_sizes, int n_in,
                              void* d_out, int out_size) {
    const float* rays_o  = (const float*)d_in[0];
    const float* rays_d  = (const float*)d_in[1];
    const float* xyz     = (const float*)d_in[2];
    const float* fdc     = (const float*)d_in[3];
    const float* opacity = (const float*)d_in[4];
    float* out = (float*)d_out;

    k_prep<<<(NPTS + 255) / 256, 256>>>(xyz, rays_o, rays_d);
    dim3 gridMin(NRAYS / 1024, NSUB);
    k_minsub<<<gridMin, 256>>>();
    k_thresh<<<NRAYS / 256, 256>>>();
    k_emit<<<NRAYS / 8, 256>>>();
    k_shade<<<NRAYS / 8, 256>>>(opacity, fdc, out);
}